// round 8
// baseline (speedup 1.0000x reference)
#include <cuda_runtime.h>
#include <math.h>

#define Bn 64
#define Cn 3
#define Hn 512
#define Wn 512
#define HW (Hn * Wn)
#define CHW (Cn * HW)
#define CUT_H 256
#define CUT_W 256

#define TILE 16
#define NTILES 1024        // 32x32 tiles per batch
#define SBH 29             // max staged rows
#define SBW 36             // smem row stride (mult of 4)
#define SCH (SBH * SBW)

struct __align__(16) BatchParams {
    float Ax, Bx, Cx, Ay, By, Cy;   // fx = Ax*x + Bx*y + Cx (flip folded in)
    float bb, cc, ss;
    int   cut, y0, x0;
    int   vec, pad0, pad1, pad2;
};

__device__ BatchParams g_params[Bn];
__device__ int4 g_tile[Bn * NTILES];   // per-tile: {xa, ys0, rows, interior}

__global__ void precompute_params_kernel(
    const float* __restrict__ u_angle, const float* __restrict__ u_scale,
    const float* __restrict__ u_trans, const float* __restrict__ u_bright,
    const float* __restrict__ u_contrast, const float* __restrict__ u_sat,
    const int* __restrict__ m_flip, const int* __restrict__ m_rot,
    const int* __restrict__ m_scale, const int* __restrict__ m_trans,
    const int* __restrict__ m_bright, const int* __restrict__ m_contrast,
    const int* __restrict__ m_sat, const int* __restrict__ m_cut,
    const int* __restrict__ y0, const int* __restrict__ x0)
{
    int b = threadIdx.x;
    if (b >= Bn) return;
    const float PI = 3.14159265358979323846f;
    float angle = (m_rot[b] > 0) ? (u_angle[b] * 2.0f - 1.0f) * PI : 0.0f;
    float sc    = (m_scale[b] > 0) ? (u_scale[b] * 2.0f - 1.0f) * 0.2f + 1.0f : 1.0f;
    float tr    = (m_trans[b] > 0) ? (u_trans[b] * 2.0f - 1.0f) * 0.125f : 0.0f;
    float ca = cosf(angle);
    float sa = sinf(angle);
    const float m00 = sc * ca, m01 = -sc * sa;
    const float m10 = sc * sa, m11 =  sc * ca;

    const float S = 512.0f / 511.0f;
    float Ax = m00 * S, Bx = m01 * S;
    float Cx = (tr - m00 - m01) * 256.0f + 255.5f;
    float Ay = m10 * S, By = m11 * S;
    float Cy = (tr - m10 - m11) * 256.0f + 255.5f;

    // Flip folded via mirror: bilinear-reflect commutes with x -> 511-x.
    if (m_flip[b] > 0) {
        Ax = -Ax; Bx = -Bx; Cx = 511.0f - Cx;
    }

    BatchParams p;
    p.Ax = Ax; p.Bx = Bx; p.Cx = Cx;
    p.Ay = Ay; p.By = By; p.Cy = Cy;
    p.bb = (m_bright[b]   > 0) ? u_bright[b] * 0.2f   : 0.0f;
    p.cc = (m_contrast[b] > 0) ? u_contrast[b] + 0.5f : 1.0f;
    p.ss = (m_sat[b]      > 0) ? u_sat[b] * 2.0f      : 1.0f;
    p.cut = m_cut[b];
    p.y0 = y0[b];
    p.x0 = x0[b];
    p.vec = (m_rot[b] > 0) ? 1 : 0;
    p.pad0 = p.pad1 = p.pad2 = 0;
    g_params[b] = p;
}

__device__ __forceinline__ float reflect_coord(float v, float size) {
    v = fabsf(v + 0.5f);
    v = fmodf(v, 2.0f * size);
    v = fminf(v, 2.0f * size - v);
    return fminf(fmaxf(v - 0.5f, 0.0f), size - 1.0f);
}

// Covering interval of reflect([a,b]) for ranges much narrower than 512.
__device__ __forceinline__ void reflect_range(float a, float b,
                                              float& lo, float& hi) {
    const float ra = reflect_coord(a, 512.0f);
    const float rb = reflect_coord(b, 512.0f);
    lo = fminf(ra, rb);
    hi = fmaxf(ra, rb);
    if (a < -0.5f && b > -0.5f)   lo = 0.0f;
    if (a < 511.5f && b > 511.5f) hi = 511.0f;
}

// Per-tile uniform setup: bbox, reflected staging window, interior flag.
__global__ void tile_setup_kernel() {
    const int gid = blockIdx.x * 256 + threadIdx.x;   // 65536 total
    const int b = gid >> 10;
    const int t = gid & (NTILES - 1);
    const BatchParams p = g_params[b];

    const int tx0 = (t & 31) << 4;
    const int ty0 = (t >> 5) << 4;
    const float xA = (float)tx0, xB = (float)(tx0 + TILE - 1);
    const float yA = (float)ty0, yB = (float)(ty0 + TILE - 1);
    const float rxa = fminf(p.Ax * xA, p.Ax * xB) + fminf(p.Bx * yA, p.Bx * yB) + p.Cx - 0.01f;
    const float rxb = fmaxf(p.Ax * xA, p.Ax * xB) + fmaxf(p.Bx * yA, p.Bx * yB) + p.Cx + 0.01f;
    const float rya = fminf(p.Ay * xA, p.Ay * xB) + fminf(p.By * yA, p.By * yB) + p.Cy - 0.01f;
    const float ryb = fmaxf(p.Ay * xA, p.Ay * xB) + fmaxf(p.By * yA, p.By * yB) + p.Cy + 0.01f;

    const int interior = (rxa >= 0.0f && rxb < 511.0f &&
                          rya >= 0.0f && ryb < 511.0f) ? 1 : 0;

    float lox, hix, loy, hiy;
    reflect_range(rxa, rxb, lox, hix);
    reflect_range(rya, ryb, loy, hiy);

    const int xa   = ((int)floorf(lox)) & ~3;
    const int ys0  = (int)floorf(loy);
    const int rows = min((int)floorf(hiy) + 2 - ys0, SBH);

    g_tile[gid] = make_int4(xa, ys0, rows, interior);
}

__device__ __forceinline__ float clip1(float v) {
    return fminf(fmaxf(v, -1.0f), 1.0f);
}

__device__ __forceinline__ void color_and_store(
    float r0, float r1, float r2, const BatchParams& p,
    float* __restrict__ out, unsigned oi)
{
    r0 = clip1(clip1(r0 + p.bb) * p.cc);
    r1 = clip1(clip1(r1 + p.bb) * p.cc);
    r2 = clip1(clip1(r2 + p.bb) * p.cc);
    const float gray = (r0 + r1 + r2) * (1.0f / 3.0f);
    r0 = clip1(gray + p.ss * (r0 - gray));
    r1 = clip1(gray + p.ss * (r1 - gray));
    r2 = clip1(gray + p.ss * (r2 - gray));
    out[oi]            = r0;
    out[oi + HW]       = r1;
    out[oi + 2 * HW]   = r2;
}

__global__ void __launch_bounds__(256, 8) augment_kernel(
    const float* __restrict__ images,
    const float* __restrict__ noise,
    float* __restrict__ out)
{
    __shared__ __align__(16) float s_img[Cn * SCH];   // 12.5 KB

    const int b = blockIdx.y;
    const BatchParams p = g_params[b];

    const int tx0 = (blockIdx.x & 31) << 4;
    const int ty0 = (blockIdx.x >> 5) << 4;

    const int tid  = threadIdx.x;
    const int lane = tid & 31;
    const int warp = tid >> 5;
    const int x = tx0 + (lane & 15);
    const int y = ty0 + (warp << 1) + (lane >> 4);

    const unsigned img_base = (unsigned)b * CHW;
    const unsigned oi = img_base + (unsigned)y * Wn + x;

    // ---- full-cut tile: float4 noise copy ----
    if (p.cut > 0 &&
        tx0 >= p.x0 && tx0 + TILE <= p.x0 + CUT_W &&
        ty0 >= p.y0 && ty0 + TILE <= p.y0 + CUT_H) {
        if (tid < 192) {
            const int ch = tid >> 6;
            const int rem = tid & 63;
            const unsigned a = img_base + (unsigned)ch * HW +
                               (unsigned)(ty0 + (rem >> 2)) * Wn + tx0 + ((rem & 3) << 2);
            *(float4*)(out + a) = *(const float4*)(noise + a);
        }
        return;
    }

    const bool incut = (p.cut > 0) &&
        (y >= p.y0) && (y < p.y0 + CUT_H) &&
        (x >= p.x0) && (x < p.x0 + CUT_W);

    // Per-tile uniform setup (one broadcast LDG.128 per block).
    const int4 ti = __ldg(&g_tile[b * NTILES + blockIdx.x]);

    if (p.vec) {
        // ================= staged path: ALL rotated tiles =================
        const int xa = ti.x, ys0 = ti.y, rows = ti.z, interior = ti.w;

        if (tid < (rows << 3)) {
            const int r  = tid >> 3;
            const int c4 = tid & 7;
            const int gy = min(ys0 + r, Hn - 1);
            const int gx = min(xa + (c4 << 2), Wn - 4);
            const unsigned ga = img_base + (unsigned)gy * Wn + gx;
            const int      sa = r * SBW + (c4 << 2);
            *(float4*)&s_img[sa]           = *(const float4*)(images + ga);
            *(float4*)&s_img[SCH + sa]     = *(const float4*)(images + ga + HW);
            *(float4*)&s_img[2 * SCH + sa] = *(const float4*)(images + ga + 2 * HW);
        }
        __syncthreads();

        if (incut) {
            out[oi]          = noise[oi];
            out[oi + HW]     = noise[oi + HW];
            out[oi + 2 * HW] = noise[oi + 2 * HW];
            return;
        }

        float fx = p.Ax * (float)x + p.Bx * (float)y + p.Cx;
        float fy = p.Ay * (float)x + p.By * (float)y + p.Cy;
        if (!interior) {            // block-uniform
            fx = reflect_coord(fx, (float)Wn);
            fy = reflect_coord(fy, (float)Hn);
        }
        const float x0f = floorf(fx);
        const float y0f = floorf(fy);
        const float wx = fx - x0f;
        const float wy = fy - y0f;
        const int base = ((int)y0f - ys0) * SBW + ((int)x0f - xa);

        float r[Cn];
        #pragma unroll
        for (int c = 0; c < Cn; c++) {
            const float* sp = s_img + c * SCH + base;
            const float v00 = sp[0];
            const float v01 = sp[1];
            const float v10 = sp[SBW];
            const float v11 = sp[SBW + 1];
            const float top = v00 + wx * (v01 - v00);
            const float bot = v10 + wx * (v11 - v10);
            r[c] = top + wy * (bot - top);
        }
        color_and_store(r[0], r[1], r[2], p, out, oi);
    } else {
        // ================= scalar path: unrotated batches =================
        if (incut) {
            out[oi]          = noise[oi];
            out[oi + HW]     = noise[oi + HW];
            out[oi + 2 * HW] = noise[oi + 2 * HW];
            return;
        }

        float fx = p.Ax * (float)x + p.Bx * (float)y + p.Cx;
        float fy = p.Ay * (float)x + p.By * (float)y + p.Cy;

        int xi0, xi1, yi0, yi1;
        if (ti.w) {                 // interior tile: no reflect, no clamps
            const float x0f = floorf(fx);
            const float y0f = floorf(fy);
            fx -= x0f; fy -= y0f;   // now wx, wy
            xi0 = (int)x0f; xi1 = xi0 + 1;
            yi0 = (int)y0f; yi1 = yi0 + 1;
        } else {
            fx = reflect_coord(fx, (float)Wn);
            fy = reflect_coord(fy, (float)Hn);
            const float x0f = floorf(fx);
            const float y0f = floorf(fy);
            fx -= x0f; fy -= y0f;
            xi0 = (int)x0f; xi1 = min(xi0 + 1, Wn - 1);
            yi0 = (int)y0f; yi1 = min(yi0 + 1, Hn - 1);
        }
        const float wx = fx, wy = fy;

        const unsigned o00 = (unsigned)yi0 * Wn + xi0;
        const unsigned o01 = (unsigned)yi0 * Wn + xi1;
        const unsigned o10 = (unsigned)yi1 * Wn + xi0;
        const unsigned o11 = (unsigned)yi1 * Wn + xi1;

        float v00[Cn], v01[Cn], v10[Cn], v11[Cn];
        #pragma unroll
        for (int c = 0; c < Cn; c++) {
            const float* ic = images + img_base + (unsigned)c * HW;
            v00[c] = __ldg(ic + o00);
            v01[c] = __ldg(ic + o01);
            v10[c] = __ldg(ic + o10);
            v11[c] = __ldg(ic + o11);
        }
        float r[Cn];
        #pragma unroll
        for (int c = 0; c < Cn; c++) {
            const float top = v00[c] + wx * (v01[c] - v00[c]);
            const float bot = v10[c] + wx * (v11[c] - v10[c]);
            r[c] = top + wy * (bot - top);
        }
        color_and_store(r[0], r[1], r[2], p, out, oi);
    }
}

extern "C" void kernel_launch(void* const* d_in, const int* in_sizes, int n_in,
                              void* d_out, int out_size) {
    const float* images     = (const float*)d_in[0];
    const float* u_angle    = (const float*)d_in[1];
    const float* u_scale    = (const float*)d_in[2];
    const float* u_trans    = (const float*)d_in[3];
    const float* u_bright   = (const float*)d_in[4];
    const float* u_contrast = (const float*)d_in[5];
    const float* u_sat      = (const float*)d_in[6];
    const float* noise      = (const float*)d_in[7];
    const int*   m_flip     = (const int*)d_in[8];
    const int*   m_rot      = (const int*)d_in[9];
    const int*   m_scale    = (const int*)d_in[10];
    const int*   m_trans    = (const int*)d_in[11];
    const int*   m_bright   = (const int*)d_in[12];
    const int*   m_contrast = (const int*)d_in[13];
    const int*   m_sat      = (const int*)d_in[14];
    const int*   m_cut      = (const int*)d_in[15];
    const int*   y0         = (const int*)d_in[16];
    const int*   x0         = (const int*)d_in[17];
    float* out = (float*)d_out;

    precompute_params_kernel<<<1, 64>>>(
        u_angle, u_scale, u_trans, u_bright, u_contrast, u_sat,
        m_flip, m_rot, m_scale, m_trans, m_bright, m_contrast,
        m_sat, m_cut, y0, x0);

    tile_setup_kernel<<<256, 256>>>();

    dim3 block(256);
    dim3 grid(NTILES, Bn);
    augment_kernel<<<grid, block>>>(images, noise, out);
}

// round 9
// speedup vs baseline: 1.1421x; 1.1421x over previous
#include <cuda_runtime.h>
#include <math.h>

#define Bn 64
#define Cn 3
#define Hn 512
#define Wn 512
#define HW (Hn * Wn)
#define CHW (Cn * HW)
#define CUT_H 256
#define CUT_W 256

#define TW 32              // tile width (x)
#define TH 16              // tile height (y)
#define NTILES 512         // (512/32)*(512/16) tiles per batch
#define SBH 45             // max staged rows
#define SBW 44             // smem row stride (11 float4)
#define SCH (SBH * SBW)    // 1980 floats per channel

struct __align__(16) BatchParams {
    float Ax, Bx, Cx, Ay, By, Cy;   // fx = Ax*x + Bx*y + Cx (flip folded in)
    float bb, cc, ss;
    int   cut, y0, x0;
    int   vec, pad0, pad1, pad2;
};

__device__ BatchParams g_params[Bn];
__device__ int4 g_tile[Bn * NTILES];   // {xa, ys0, rows, interior}

__device__ __forceinline__ float reflect_coord(float v, float size) {
    v = fabsf(v + 0.5f);
    v = fmodf(v, 2.0f * size);
    v = fminf(v, 2.0f * size - v);
    return fminf(fmaxf(v - 0.5f, 0.0f), size - 1.0f);
}

// Covering interval of reflect([a,b]) for ranges much narrower than 512.
__device__ __forceinline__ void reflect_range(float a, float b,
                                              float& lo, float& hi) {
    const float ra = reflect_coord(a, 512.0f);
    const float rb = reflect_coord(b, 512.0f);
    lo = fminf(ra, rb);
    hi = fmaxf(ra, rb);
    if (a < -0.5f && b > -0.5f)   lo = 0.0f;
    if (a < 511.5f && b > 511.5f) hi = 511.0f;
}

// ONE setup kernel: per-batch params (computed redundantly, cheap) + per-tile
// staging window. 64*512 threads in 128 blocks.
__global__ void setup_kernel(
    const float* __restrict__ u_angle, const float* __restrict__ u_scale,
    const float* __restrict__ u_trans, const float* __restrict__ u_bright,
    const float* __restrict__ u_contrast, const float* __restrict__ u_sat,
    const int* __restrict__ m_flip, const int* __restrict__ m_rot,
    const int* __restrict__ m_scale, const int* __restrict__ m_trans,
    const int* __restrict__ m_bright, const int* __restrict__ m_contrast,
    const int* __restrict__ m_sat, const int* __restrict__ m_cut,
    const int* __restrict__ y0, const int* __restrict__ x0)
{
    const int gid = blockIdx.x * 256 + threadIdx.x;
    const int b = gid >> 9;
    const int t = gid & (NTILES - 1);

    const float PI = 3.14159265358979323846f;
    const float angle = (m_rot[b] > 0) ? (u_angle[b] * 2.0f - 1.0f) * PI : 0.0f;
    const float sc    = (m_scale[b] > 0) ? (u_scale[b] * 2.0f - 1.0f) * 0.2f + 1.0f : 1.0f;
    const float tr    = (m_trans[b] > 0) ? (u_trans[b] * 2.0f - 1.0f) * 0.125f : 0.0f;
    const float ca = cosf(angle);
    const float sa = sinf(angle);
    const float m00 = sc * ca, m01 = -sc * sa;
    const float m10 = sc * sa, m11 =  sc * ca;

    const float S = 512.0f / 511.0f;
    float Ax = m00 * S, Bx = m01 * S;
    float Cx = (tr - m00 - m01) * 256.0f + 255.5f;
    float Ay = m10 * S, By = m11 * S;
    float Cy = (tr - m10 - m11) * 256.0f + 255.5f;
    if (m_flip[b] > 0) {            // flip folded via mirror (commutes)
        Ax = -Ax; Bx = -Bx; Cx = 511.0f - Cx;
    }

    if (t == 0) {
        BatchParams p;
        p.Ax = Ax; p.Bx = Bx; p.Cx = Cx;
        p.Ay = Ay; p.By = By; p.Cy = Cy;
        p.bb = (m_bright[b]   > 0) ? u_bright[b] * 0.2f   : 0.0f;
        p.cc = (m_contrast[b] > 0) ? u_contrast[b] + 0.5f : 1.0f;
        p.ss = (m_sat[b]      > 0) ? u_sat[b] * 2.0f      : 1.0f;
        p.cut = m_cut[b];
        p.y0 = y0[b];
        p.x0 = x0[b];
        p.vec = (m_rot[b] > 0) ? 1 : 0;
        p.pad0 = p.pad1 = p.pad2 = 0;
        g_params[b] = p;
    }

    const int tx0 = (t & 15) << 5;
    const int ty0 = (t >> 4) << 4;
    const float xA = (float)tx0, xB = (float)(tx0 + TW - 1);
    const float yA = (float)ty0, yB = (float)(ty0 + TH - 1);
    const float rxa = fminf(Ax * xA, Ax * xB) + fminf(Bx * yA, Bx * yB) + Cx - 0.01f;
    const float rxb = fmaxf(Ax * xA, Ax * xB) + fmaxf(Bx * yA, Bx * yB) + Cx + 0.01f;
    const float rya = fminf(Ay * xA, Ay * xB) + fminf(By * yA, By * yB) + Cy - 0.01f;
    const float ryb = fmaxf(Ay * xA, Ay * xB) + fmaxf(By * yA, By * yB) + Cy + 0.01f;

    const int interior = (rxa >= 0.0f && rxb < 511.0f &&
                          rya >= 0.0f && ryb < 511.0f) ? 1 : 0;

    float lox, hix, loy, hiy;
    reflect_range(rxa, rxb, lox, hix);
    reflect_range(rya, ryb, loy, hiy);

    const int xa   = ((int)floorf(lox)) & ~3;
    const int ys0  = (int)floorf(loy);
    const int rows = min((int)floorf(hiy) + 2 - ys0, SBH);

    g_tile[gid] = make_int4(xa, ys0, rows, interior);
}

__device__ __forceinline__ float clip1(float v) {
    return fminf(fmaxf(v, -1.0f), 1.0f);
}

__device__ __forceinline__ void colorize(float r[3], const BatchParams& p) {
    r[0] = clip1(clip1(r[0] + p.bb) * p.cc);
    r[1] = clip1(clip1(r[1] + p.bb) * p.cc);
    r[2] = clip1(clip1(r[2] + p.bb) * p.cc);
    const float gray = (r[0] + r[1] + r[2]) * (1.0f / 3.0f);
    r[0] = clip1(gray + p.ss * (r[0] - gray));
    r[1] = clip1(gray + p.ss * (r[1] - gray));
    r[2] = clip1(gray + p.ss * (r[2] - gray));
}

__device__ __forceinline__ void sample_smem(
    const float* __restrict__ s, int base, float wx, float wy, float r[3]) {
    #pragma unroll
    for (int c = 0; c < Cn; c++) {
        const float* sp = s + c * SCH + base;
        const float v00 = sp[0];
        const float v01 = sp[1];
        const float v10 = sp[SBW];
        const float v11 = sp[SBW + 1];
        const float top = v00 + wx * (v01 - v00);
        const float bot = v10 + wx * (v11 - v10);
        r[c] = top + wy * (bot - top);
    }
}

__device__ __forceinline__ void gather_gmem(
    const float* __restrict__ img, unsigned img_base,
    float fx, float fy, bool interior, float r[3]) {
    if (!interior) {
        fx = reflect_coord(fx, (float)Wn);
        fy = reflect_coord(fy, (float)Hn);
    }
    const float x0f = floorf(fx);
    const float y0f = floorf(fy);
    const float wx = fx - x0f;
    const float wy = fy - y0f;
    const int xi0 = (int)x0f;
    const int yi0 = (int)y0f;
    const int xi1 = interior ? xi0 + 1 : min(xi0 + 1, Wn - 1);
    const int yi1 = interior ? yi0 + 1 : min(yi0 + 1, Hn - 1);
    const unsigned o00 = (unsigned)yi0 * Wn + xi0;
    const unsigned o01 = (unsigned)yi0 * Wn + xi1;
    const unsigned o10 = (unsigned)yi1 * Wn + xi0;
    const unsigned o11 = (unsigned)yi1 * Wn + xi1;
    #pragma unroll
    for (int c = 0; c < Cn; c++) {
        const float* ic = img + img_base + (unsigned)c * HW;
        const float v00 = __ldg(ic + o00);
        const float v01 = __ldg(ic + o01);
        const float v10 = __ldg(ic + o10);
        const float v11 = __ldg(ic + o11);
        const float top = v00 + wx * (v01 - v00);
        const float bot = v10 + wx * (v11 - v10);
        r[c] = top + wy * (bot - top);
    }
}

__global__ void __launch_bounds__(256) augment_kernel(
    const float* __restrict__ images,
    const float* __restrict__ noise,
    float* __restrict__ out)
{
    __shared__ __align__(16) float s_img[Cn * SCH];   // 23.8 KB

    const int b = blockIdx.y;
    const BatchParams p = g_params[b];

    const int t   = blockIdx.x;
    const int tx0 = (t & 15) << 5;
    const int ty0 = (t >> 4) << 4;

    const int tid = threadIdx.x;
    const int x = tx0 + ((tid & 15) << 1);   // 2 px/thread: x, x+1
    const int y = ty0 + (tid >> 4);

    const unsigned img_base = (unsigned)b * CHW;
    const unsigned oi = img_base + (unsigned)y * Wn + x;

    // ---- full-cut tile: float4 noise copy ----
    if (p.cut > 0 &&
        tx0 >= p.x0 && tx0 + TW <= p.x0 + CUT_W &&
        ty0 >= p.y0 && ty0 + TH <= p.y0 + CUT_H) {
        #pragma unroll
        for (int i = tid; i < 384; i += 256) {      // 3ch * 16 rows * 8 f4
            const int ch  = i >> 7;
            const int rem = i & 127;
            const unsigned a = img_base + (unsigned)ch * HW +
                               (unsigned)(ty0 + (rem >> 3)) * Wn + tx0 + ((rem & 7) << 2);
            *(float4*)(out + a) = *(const float4*)(noise + a);
        }
        return;
    }

    const int4 ti = __ldg(&g_tile[b * NTILES + t]);

    float fx0 = p.Ax * (float)x + p.Bx * (float)y + p.Cx;
    float fy0 = p.Ay * (float)x + p.By * (float)y + p.Cy;
    float fx1 = fx0 + p.Ax;
    float fy1 = fy0 + p.Ay;

    float r0[3], r1[3];

    if (p.vec) {
        // ================= staged path: ALL rotated tiles =================
        const int xa = ti.x, ys0 = ti.y, rows = ti.z;
        const bool interior = ti.w != 0;

        for (int i = tid; i < rows * 11; i += 256) {
            const int rr = i / 11;
            const int c4 = i - rr * 11;
            const int gy = min(ys0 + rr, Hn - 1);
            const int gx = min(xa + (c4 << 2), Wn - 4);
            const unsigned ga = img_base + (unsigned)gy * Wn + gx;
            const int      sa = rr * SBW + (c4 << 2);
            *(float4*)&s_img[sa]           = *(const float4*)(images + ga);
            *(float4*)&s_img[SCH + sa]     = *(const float4*)(images + ga + HW);
            *(float4*)&s_img[2 * SCH + sa] = *(const float4*)(images + ga + 2 * HW);
        }
        __syncthreads();

        if (!interior) {            // block-uniform
            fx0 = reflect_coord(fx0, (float)Wn);
            fy0 = reflect_coord(fy0, (float)Hn);
            fx1 = reflect_coord(fx1, (float)Wn);
            fy1 = reflect_coord(fy1, (float)Hn);
        }
        {
            const float x0f = floorf(fx0), y0f = floorf(fy0);
            const int base = ((int)y0f - ys0) * SBW + ((int)x0f - xa);
            sample_smem(s_img, base, fx0 - x0f, fy0 - y0f, r0);
        }
        {
            const float x0f = floorf(fx1), y0f = floorf(fy1);
            const int base = ((int)y0f - ys0) * SBW + ((int)x0f - xa);
            sample_smem(s_img, base, fx1 - x0f, fy1 - y0f, r1);
        }
    } else {
        // ================= scalar path: unrotated batches =================
        const bool interior = ti.w != 0;
        gather_gmem(images, img_base, fx0, fy0, interior, r0);
        gather_gmem(images, img_base, fx1, fy1, interior, r1);
    }

    colorize(r0, p);
    colorize(r1, p);

    // ---- cutout overrides (per pixel) ----
    if (p.cut > 0 && y >= p.y0 && y < p.y0 + CUT_H) {
        if (x >= p.x0 && x < p.x0 + CUT_W) {
            r0[0] = noise[oi];
            r0[1] = noise[oi + HW];
            r0[2] = noise[oi + 2 * HW];
        }
        if (x + 1 >= p.x0 && x + 1 < p.x0 + CUT_W) {
            r1[0] = noise[oi + 1];
            r1[1] = noise[oi + 1 + HW];
            r1[2] = noise[oi + 1 + 2 * HW];
        }
    }

    *(float2*)(out + oi)          = make_float2(r0[0], r1[0]);
    *(float2*)(out + oi + HW)     = make_float2(r0[1], r1[1]);
    *(float2*)(out + oi + 2 * HW) = make_float2(r0[2], r1[2]);
}

extern "C" void kernel_launch(void* const* d_in, const int* in_sizes, int n_in,
                              void* d_out, int out_size) {
    const float* images     = (const float*)d_in[0];
    const float* u_angle    = (const float*)d_in[1];
    const float* u_scale    = (const float*)d_in[2];
    const float* u_trans    = (const float*)d_in[3];
    const float* u_bright   = (const float*)d_in[4];
    const float* u_contrast = (const float*)d_in[5];
    const float* u_sat      = (const float*)d_in[6];
    const float* noise      = (const float*)d_in[7];
    const int*   m_flip     = (const int*)d_in[8];
    const int*   m_rot      = (const int*)d_in[9];
    const int*   m_scale    = (const int*)d_in[10];
    const int*   m_trans    = (const int*)d_in[11];
    const int*   m_bright   = (const int*)d_in[12];
    const int*   m_contrast = (const int*)d_in[13];
    const int*   m_sat      = (const int*)d_in[14];
    const int*   m_cut      = (const int*)d_in[15];
    const int*   y0         = (const int*)d_in[16];
    const int*   x0         = (const int*)d_in[17];
    float* out = (float*)d_out;

    setup_kernel<<<(Bn * NTILES) / 256, 256>>>(
        u_angle, u_scale, u_trans, u_bright, u_contrast, u_sat,
        m_flip, m_rot, m_scale, m_trans, m_bright, m_contrast,
        m_sat, m_cut, y0, x0);

    dim3 block(256);
    dim3 grid(NTILES, Bn);
    augment_kernel<<<grid, block>>>(images, noise, out);
}